// round 1
// baseline (speedup 1.0000x reference)
#include <cuda_runtime.h>
#include <cuda_bf16.h>

// Circular self-convolution: out[b,k] = sum_j x[b,j] * x[b,(k-j) mod N]
// N = 1024, B = 128, three independent input arrays.
//
// Strategy: one CTA per (array, row). Row cached in smem twice:
//   SX[j]  = x[j]                       (broadcast operand)
//   E[u]   = x[(u + 1021) mod 1024]     (extended/phase-shifted circular copy,
//                                        so 8-wide windows are two aligned float4s)
// Each thread computes 4 consecutive outputs; inner loop register-blocks
// 4 outputs x 4 j-steps = 16 FFMA per iteration with 3 LDS.128.

#define N_CONV 1024
#define THREADS 256

__global__ __launch_bounds__(THREADS, 4)
void mcf_conv_kernel(const float* __restrict__ x1,
                     const float* __restrict__ x2,
                     const float* __restrict__ x3,
                     float* __restrict__ out)
{
    __shared__ __align__(16) float SX[N_CONV];
    __shared__ __align__(16) float E[2052];

    const int bx  = blockIdx.x;
    const int arr = bx >> 7;        // 0..2 : which input array
    const int row = bx & 127;       // 0..127 : batch row

    const float* x = (arr == 0) ? x1 : ((arr == 1) ? x2 : x3);
    const float* xr = x + (size_t)row * N_CONV;

    const int tid = threadIdx.x;

    // Load row into SX (coalesced float4).
    float4 v = ((const float4*)xr)[tid];
    ((float4*)SX)[tid] = v;
    __syncthreads();

    // Build extended circular copy: E[u] = x[(u + 1021) mod 1024], u in [0, 2052).
    // Derivation: window value w[m] = x[(k0 - j4 - 3 + m) mod N] must equal
    // E[(k0 - j4 + 1024) + m], which holds with phase A = -3 mod 1024 = 1021.
    for (int u = tid; u < 2052; u += THREADS)
        E[u] = SX[(u + 1021) & (N_CONV - 1)];
    __syncthreads();

    const int k0 = tid * 4;         // this thread's 4 consecutive outputs
    float a0 = 0.f, a1 = 0.f, a2 = 0.f, a3 = 0.f;

    #pragma unroll 4
    for (int j4 = 0; j4 < N_CONV; j4 += 4) {
        // x[j4 .. j4+3] — same address for all threads (smem broadcast)
        float4 xa = *(const float4*)&SX[j4];

        // 8-value window, aligned: base index (k0 - j4 + 1024) is multiple of 4
        const float* ep = &E[k0 - j4 + 1024];
        float4 w0 = *(const float4*)(ep);       // w[0..3]
        float4 w1 = *(const float4*)(ep + 4);   // w[4..7]

        // out[k0+i] += sum_jj xa[jj] * w[i - jj + 3]
        a0 += xa.x * w0.w;  a0 += xa.y * w0.z;  a0 += xa.z * w0.y;  a0 += xa.w * w0.x;
        a1 += xa.x * w1.x;  a1 += xa.y * w0.w;  a1 += xa.z * w0.z;  a1 += xa.w * w0.y;
        a2 += xa.x * w1.y;  a2 += xa.y * w1.x;  a2 += xa.z * w0.w;  a2 += xa.w * w0.z;
        a3 += xa.x * w1.z;  a3 += xa.y * w1.y;  a3 += xa.z * w1.x;  a3 += xa.w * w0.w;
    }

    float4 o = make_float4(a0, a1, a2, a3);
    float* orow = out + (size_t)arr * 128 * N_CONV + (size_t)row * N_CONV;
    ((float4*)orow)[tid] = o;
}

extern "C" void kernel_launch(void* const* d_in, const int* in_sizes, int n_in,
                              void* d_out, int out_size)
{
    const float* x1 = (const float*)d_in[0];
    const float* x2 = (const float*)d_in[1];
    const float* x3 = (const float*)d_in[2];
    float* out = (float*)d_out;

    mcf_conv_kernel<<<384, THREADS>>>(x1, x2, x3, out);
}

// round 2
// speedup vs baseline: 1.2549x; 1.2549x over previous
#include <cuda_runtime.h>
#include <cuda_bf16.h>

// Circular self-convolution: out[b,k] = sum_j x[b,j] * x[b,(k-j) mod N]
// N = 1024, B = 128, three input arrays. One CTA (128 threads) per (array,row).
//
// Register tile: each thread computes T=8 consecutive outputs; inner loop
// processes J=8 j-values per iteration -> 64 FMAs per (4 window LDS.128 +
// 2 broadcast LDS.128). This moves the kernel from shared-crossbar-bound
// (old 3 B/FMA) to FMA/issue-bound (1.5 B/FMA).
//
// smem holds only the extended circular array:
//   E[u] = x[(u - 8) mod 1024],  u in [0, 2056)
// Window for j-block j8: w[m] = E[ub + m], ub = k0 - j8 + 1024 (multiple of 8,
// so all window float4 loads are aligned). Broadcast operand x[j] = E[j + 8].

#define N_CONV 1024
#define THREADS 128

__global__ __launch_bounds__(THREADS, 8)
void mcf_conv_kernel(const float* __restrict__ x1,
                     const float* __restrict__ x2,
                     const float* __restrict__ x3,
                     float* __restrict__ out)
{
    __shared__ __align__(16) float E[2064];   // 2056 used, padded

    const int bx  = blockIdx.x;
    const int arr = bx >> 7;        // which input array
    const int row = bx & 127;       // batch row

    const float* x  = (arr == 0) ? x1 : ((arr == 1) ? x2 : x3);
    const float* xr = x + (size_t)row * N_CONV;

    const int tid = threadIdx.x;

    // Build E[u] = x[(u - 8) mod 1024] = x[(u + 1016) mod 1024], 2056 floats.
    // Per float4: start s = (u4*4 + 1016) & 1023 is a multiple of 4, never
    // crosses the wrap (max s = 1020 -> covers 1020..1023). Coalesced.
    float4* E4 = (float4*)E;
    #pragma unroll
    for (int u4 = tid; u4 < 514; u4 += THREADS)
        E4[u4] = *(const float4*)&xr[(u4 * 4 + 1016) & (N_CONV - 1)];
    __syncthreads();

    const int k0 = tid * 8;         // this thread's 8 consecutive outputs

    float a[8];
    #pragma unroll
    for (int t = 0; t < 8; ++t) a[t] = 0.f;

    // Window pointer: starts at E[k0 + 1024] (j8 = 0), steps down 8 floats/iter.
    const float4* wp = (const float4*)&E[k0 + N_CONV];
    // Broadcast pointer: xa[jj] = x[j8 + jj] = E[j8 + 8 + jj].
    const float*  bp = &E[8];

    #pragma unroll 4
    for (int it = 0; it < N_CONV / 8; ++it) {
        float4 W0 = wp[0], W1 = wp[1], W2 = wp[2], W3 = wp[3];
        float4 B0 = *(const float4*)(bp);
        float4 B1 = *(const float4*)(bp + 4);

        float wv[16];
        wv[ 0] = W0.x; wv[ 1] = W0.y; wv[ 2] = W0.z; wv[ 3] = W0.w;
        wv[ 4] = W1.x; wv[ 5] = W1.y; wv[ 6] = W1.z; wv[ 7] = W1.w;
        wv[ 8] = W2.x; wv[ 9] = W2.y; wv[10] = W2.z; wv[11] = W2.w;
        wv[12] = W3.x; wv[13] = W3.y; wv[14] = W3.z; wv[15] = W3.w;

        float xa[8];
        xa[0] = B0.x; xa[1] = B0.y; xa[2] = B0.z; xa[3] = B0.w;
        xa[4] = B1.x; xa[5] = B1.y; xa[6] = B1.z; xa[7] = B1.w;

        // a[t] += x[j8+jj] * x[(k0 + t - j8 - jj) mod N]
        //       = xa[jj] * wv[8 + t - jj]
        #pragma unroll
        for (int jj = 0; jj < 8; ++jj) {
            #pragma unroll
            for (int t = 0; t < 8; ++t)
                a[t] = fmaf(xa[jj], wv[8 + t - jj], a[t]);
        }

        wp -= 2;   // window base moves down 8 floats
        bp += 8;   // next j-block
    }

    float* orow = out + (size_t)arr * 128 * N_CONV + (size_t)row * N_CONV;
    float4 o0 = make_float4(a[0], a[1], a[2], a[3]);
    float4 o1 = make_float4(a[4], a[5], a[6], a[7]);
    ((float4*)&orow[k0])[0] = o0;
    ((float4*)&orow[k0])[1] = o1;
}

extern "C" void kernel_launch(void* const* d_in, const int* in_sizes, int n_in,
                              void* d_out, int out_size)
{
    const float* x1 = (const float*)d_in[0];
    const float* x2 = (const float*)d_in[1];
    const float* x3 = (const float*)d_in[2];
    float* out = (float*)d_out;

    mcf_conv_kernel<<<384, THREADS>>>(x1, x2, x3, out);
}